// round 7
// baseline (speedup 1.0000x reference)
#include <cuda_runtime.h>
#include <cuda_bf16.h>
#include <cstdint>

// ---------------------------------------------------------------------------
// RowLSTM: x(16,64,64,64), Wi(512,64,1,3), bi(512), Wh(512,128), bh(512)
// out: (16,128,64,64) fp32
// Phase 1 (i2h): mma.sync bf16 (hi/lo split, 3-pass) GEMM -> g_i2h (no bias)
// Phase 2 (rec): fp32 scan (R4 structure, coalesced WhT), bias fused here
// ---------------------------------------------------------------------------

#define B_  16
#define C_  64
#define H_  64
#define W_  64
#define HID_ 128
#define G_  512   // 4*HID
#define K_  192   // C_*3

static __device__ float g_i2h[(size_t)H_ * B_ * W_ * G_];   // 134 MB [h][b][w][g]
static __device__ float g_WhT[(size_t)HID_ * G_];           // [k][g]

__device__ __forceinline__ float sigmf(float v) {
    return __fdividef(1.0f, 1.0f + __expf(-v));
}
__device__ __forceinline__ float tanhf_(float v) {
    return __fdividef(2.0f, 1.0f + __expf(-2.0f * v)) - 1.0f;
}

// pack two floats as bf16x2 (a -> low half)
__device__ __forceinline__ uint32_t pkbf(float a, float b) {
    __nv_bfloat162 t = __floats2bfloat162_rn(a, b);
    return *reinterpret_cast<uint32_t*>(&t);
}
__device__ __forceinline__ void split2(float v, float& hi, float& lo) {
    __nv_bfloat16 h = __float2bfloat16_rn(v);
    hi = __bfloat162float(h);
    lo = v - hi;
}

__device__ __forceinline__ void mma_bf16(float d[4], const uint32_t a[4], const uint32_t b[2]) {
    asm volatile(
        "mma.sync.aligned.m16n8k16.row.col.f32.bf16.bf16.f32 "
        "{%0,%1,%2,%3},{%4,%5,%6,%7},{%8,%9},{%0,%1,%2,%3};"
        : "+f"(d[0]), "+f"(d[1]), "+f"(d[2]), "+f"(d[3])
        : "r"(a[0]), "r"(a[1]), "r"(a[2]), "r"(a[3]), "r"(b[0]), "r"(b[1]));
}

// ---------------------------------------------------------------------------
// Kernel 0: transpose Wh -> WhT[k][g]
// ---------------------------------------------------------------------------
__global__ void prep_kernel(const float* __restrict__ Wh)
{
    int k = blockIdx.x, g = threadIdx.x;
    g_WhT[(size_t)k * G_ + g] = Wh[(size_t)g * HID_ + k];
}

// ---------------------------------------------------------------------------
// Kernel A: i2h via mma.sync bf16 (3-pass hi/lo).
// Grid 128 = gc(8 gate-chunks of 64) x b(16). 256 threads = 8 warps.
// Block: 64 gates x 128 spatial per iteration (h-pair), 32 iterations.
// smem: A_hi/A_lo fragment-linear (12 kt x 4 gt x 32 lanes x 16B),
//       B_hi/B_lo (12 kt x 16 nt x 32 lanes x 8B); staging reuses B_hi.
// ---------------------------------------------------------------------------
#define OFF_AHI 0
#define OFF_ALO 24576
#define OFF_BHI 49152
#define OFF_BLO 98304
#define SMEM_I2H 147456

__global__ void __launch_bounds__(256, 1)
i2h_kernel(const float* __restrict__ x, const float* __restrict__ Wi)
{
    extern __shared__ char sm[];
    const int gc = blockIdx.x & 7;     // 64-gate chunk
    const int b  = blockIdx.x >> 3;
    const int tid  = threadIdx.x;
    const int lane = tid & 31;
    const int warp = tid >> 5;
    const int wg   = warp >> 2;        // 0..1  gate sub (32 gates)
    const int wn   = warp & 3;         // 0..3  spatial sub (32 n)
    const int grp  = lane >> 2;
    const int tig  = lane & 3;

    // ---- fill A fragments once: Wi[gc*64 .. +64][0..192) hi/lo ----
    for (int idx = tid; idx < 12 * 4 * 32; idx += 256) {
        int kt = idx >> 7;
        int rem = idx & 127;
        int gt = rem >> 5;
        int ln = rem & 31;
        int gp = ln >> 2, tg = ln & 3;
        int g0 = gc * 64 + gt * 16 + gp;    // row for regs 0,2 (+8 for 1,3)
        int k0 = kt * 16 + 2 * tg;          // k for regs 0,1 (+8 for 2,3)
        float2 v00 = *reinterpret_cast<const float2*>(&Wi[(size_t)g0 * K_ + k0]);
        float2 v10 = *reinterpret_cast<const float2*>(&Wi[(size_t)(g0 + 8) * K_ + k0]);
        float2 v01 = *reinterpret_cast<const float2*>(&Wi[(size_t)g0 * K_ + k0 + 8]);
        float2 v11 = *reinterpret_cast<const float2*>(&Wi[(size_t)(g0 + 8) * K_ + k0 + 8]);
        float h0a, l0a, h0b, l0b, h1a, l1a, h1b, l1b;
        float h2a, l2a, h2b, l2b, h3a, l3a, h3b, l3b;
        split2(v00.x, h0a, l0a); split2(v00.y, h0b, l0b);
        split2(v10.x, h1a, l1a); split2(v10.y, h1b, l1b);
        split2(v01.x, h2a, l2a); split2(v01.y, h2b, l2b);
        split2(v11.x, h3a, l3a); split2(v11.y, h3b, l3b);
        uint4 hv = make_uint4(pkbf(h0a, h0b), pkbf(h1a, h1b), pkbf(h2a, h2b), pkbf(h3a, h3b));
        uint4 lv = make_uint4(pkbf(l0a, l0b), pkbf(l1a, l1b), pkbf(l2a, l2b), pkbf(l3a, l3b));
        uint32_t aoff = ((kt * 4 + gt) * 32 + ln) * 16;
        *reinterpret_cast<uint4*>(sm + OFF_AHI + aoff) = hv;
        *reinterpret_cast<uint4*>(sm + OFF_ALO + aoff) = lv;
    }

    float* stg = reinterpret_cast<float*>(sm + OFF_BHI);   // 128n x 64g staging

    for (int it = 0; it < 32; it++) {
        const int h0 = it * 2;
        __syncthreads();   // prior STG readers done before overwriting B regions

        // ---- fill B fragments: im2col x tile [n=hs*64+w][k], hi/lo ----
        for (int idx = tid; idx < 12 * 16 * 32; idx += 256) {
            int kt = idx >> 9;
            int rem = idx & 511;
            int nt = rem >> 5;
            int ln = rem & 31;
            int gp = ln >> 2, tg = ln & 3;
            int n = nt * 8 + gp;
            int hs = n >> 6, w = n & 63;
            const float* xrow = &x[(((size_t)b * C_) * H_ + (h0 + hs)) * W_];
            float vh[4], vl[4];
#pragma unroll
            for (int r = 0; r < 4; r++) {
                int k = kt * 16 + 2 * tg + (r >> 1) * 8 + (r & 1);
                int c = k / 3;
                int kw = k - 3 * c;
                int wsrc = w + kw - 1;
                float v = ((unsigned)wsrc < W_)
                        ? xrow[(size_t)c * (H_ * W_) + wsrc] : 0.f;
                split2(v, vh[r], vl[r]);
            }
            uint2 bhv = make_uint2(pkbf(vh[0], vh[1]), pkbf(vh[2], vh[3]));
            uint2 blv = make_uint2(pkbf(vl[0], vl[1]), pkbf(vl[2], vl[3]));
            uint32_t boff = ((kt * 16 + nt) * 32 + ln) * 8;
            *reinterpret_cast<uint2*>(sm + OFF_BHI + boff) = bhv;
            *reinterpret_cast<uint2*>(sm + OFF_BLO + boff) = blv;
        }
        __syncthreads();

        // ---- mma: warp tile 32g x 32n ----
        float d[2][4][4];
#pragma unroll
        for (int i = 0; i < 2; i++)
#pragma unroll
            for (int j = 0; j < 4; j++)
#pragma unroll
                for (int r = 0; r < 4; r++) d[i][j][r] = 0.f;

        for (int kt = 0; kt < 12; kt++) {
            uint4 ah[2], al[2];
            uint2 bh2[4], bl2[4];
#pragma unroll
            for (int gt2 = 0; gt2 < 2; gt2++) {
                uint32_t aoff = ((kt * 4 + wg * 2 + gt2) * 32 + lane) * 16;
                ah[gt2] = *reinterpret_cast<const uint4*>(sm + OFF_AHI + aoff);
                al[gt2] = *reinterpret_cast<const uint4*>(sm + OFF_ALO + aoff);
            }
#pragma unroll
            for (int nt2 = 0; nt2 < 4; nt2++) {
                uint32_t boff = ((kt * 16 + wn * 4 + nt2) * 32 + lane) * 8;
                bh2[nt2] = *reinterpret_cast<const uint2*>(sm + OFF_BHI + boff);
                bl2[nt2] = *reinterpret_cast<const uint2*>(sm + OFF_BLO + boff);
            }
            // pass 0: Ahi*Bhi; pass 1: Ahi*Blo; pass 2: Alo*Bhi
#pragma unroll
            for (int gt2 = 0; gt2 < 2; gt2++)
#pragma unroll
                for (int nt2 = 0; nt2 < 4; nt2++)
                    mma_bf16(d[gt2][nt2], &ah[gt2].x, &bh2[nt2].x);
#pragma unroll
            for (int gt2 = 0; gt2 < 2; gt2++)
#pragma unroll
                for (int nt2 = 0; nt2 < 4; nt2++)
                    mma_bf16(d[gt2][nt2], &ah[gt2].x, &bl2[nt2].x);
#pragma unroll
            for (int gt2 = 0; gt2 < 2; gt2++)
#pragma unroll
                for (int nt2 = 0; nt2 < 4; nt2++)
                    mma_bf16(d[gt2][nt2], &al[gt2].x, &bh2[nt2].x);
        }
        __syncthreads();   // all warps done reading B before staging overwrite

        // ---- stage d -> stg[n][g-local] ----
#pragma unroll
        for (int gt2 = 0; gt2 < 2; gt2++) {
            int g0 = (wg * 2 + gt2) * 16 + grp;
#pragma unroll
            for (int nt2 = 0; nt2 < 4; nt2++) {
                int n0 = (wn * 4 + nt2) * 8 + 2 * tig;
                stg[n0 * 64 + g0]           = d[gt2][nt2][0];
                stg[(n0 + 1) * 64 + g0]     = d[gt2][nt2][1];
                stg[n0 * 64 + g0 + 8]       = d[gt2][nt2][2];
                stg[(n0 + 1) * 64 + g0 + 8] = d[gt2][nt2][3];
            }
        }
        __syncthreads();

        // ---- coalesced STG: g_i2h[h][b][w][gc*64 + 0..63] ----
#pragma unroll
        for (int u = 0; u < 8; u++) {
            int idx = tid + u * 256;
            int n = idx >> 4;
            int q4 = idx & 15;
            float4 v = *reinterpret_cast<const float4*>(&stg[n * 64 + q4 * 4]);
            size_t dst = ((size_t)(h0 + (n >> 6)) * B_ + b) * (W_ * G_)
                       + (size_t)(n & 63) * G_ + gc * 64 + q4 * 4;
            *reinterpret_cast<float4*>(&g_i2h[dst]) = v;
        }
    }
}

// ---------------------------------------------------------------------------
// Kernel B: recurrent scan (R4 winner + fused bias).
// 128 blocks = (b, w-group of 8 cols), 512 threads.
// ---------------------------------------------------------------------------
#define HP 10

__global__ void __launch_bounds__(512, 1)
rec_kernel(const float* __restrict__ bi, const float* __restrict__ bh,
           float* __restrict__ out)
{
    const int b  = blockIdx.x >> 3;
    const int w0 = (blockIdx.x & 7) * 8;
    const int t  = threadIdx.x;
    const int q  = t & 127;
    const int ch = t >> 7;

    __shared__ float hbuf[HID_ * HP];
    __shared__ float cbuf[HID_ * HP];
    __shared__ float gbuf[8][G_];

    for (int p = t; p < HID_ * HP; p += 512) { hbuf[p] = 0.f; cbuf[p] = 0.f; }
    __syncthreads();

    // bias for gates 4q..4q+3
    float4 bias4;
    {
        float4 v1 = __ldg(reinterpret_cast<const float4*>(bi) + q);
        float4 v2 = __ldg(reinterpret_cast<const float4*>(bh) + q);
        bias4 = make_float4(v1.x + v2.x, v1.y + v2.y, v1.z + v2.z, v1.w + v2.w);
    }

    const float4* __restrict__ WhT4 = reinterpret_cast<const float4*>(g_WhT);

    for (int row = 0; row < H_; row++) {
        const size_t ibase = ((((size_t)row * B_ + b) * W_) + w0 + 2 * ch) * G_ + 4 * q;
        float4 gv0 = *reinterpret_cast<const float4*>(&g_i2h[ibase]);
        float4 gv1 = *reinterpret_cast<const float4*>(&g_i2h[ibase + G_]);
        gv0.x += bias4.x; gv0.y += bias4.y; gv0.z += bias4.z; gv0.w += bias4.w;
        gv1.x += bias4.x; gv1.y += bias4.y; gv1.z += bias4.z; gv1.w += bias4.w;

        float a00 = 0.f, a10 = 0.f, a20 = 0.f, a30 = 0.f;
        float a01 = 0.f, a11 = 0.f, a21 = 0.f, a31 = 0.f;

#pragma unroll 4
        for (int k = 0; k < HID_; k++) {
            float4 wv = __ldg(&WhT4[(size_t)k * (G_ / 4) + q]);
            float2 hv = *reinterpret_cast<const float2*>(&hbuf[k * HP + 2 * ch]);
            a00 = fmaf(wv.x, hv.x, a00); a01 = fmaf(wv.x, hv.y, a01);
            a10 = fmaf(wv.y, hv.x, a10); a11 = fmaf(wv.y, hv.y, a11);
            a20 = fmaf(wv.z, hv.x, a20); a21 = fmaf(wv.z, hv.y, a21);
            a30 = fmaf(wv.w, hv.x, a30); a31 = fmaf(wv.w, hv.y, a31);
        }

        *reinterpret_cast<float4*>(&gbuf[2 * ch][4 * q]) =
            make_float4(a00 + gv0.x, a10 + gv0.y, a20 + gv0.z, a30 + gv0.w);
        *reinterpret_cast<float4*>(&gbuf[2 * ch + 1][4 * q]) =
            make_float4(a01 + gv1.x, a11 + gv1.y, a21 + gv1.z, a31 + gv1.w);
        __syncthreads();

#pragma unroll
        for (int pp = 0; pp < 2; pp++) {
            int p   = t + pp * 512;
            int col = p >> 7;
            int d   = p & 127;
            float ig = gbuf[col][d];
            float fg = gbuf[col][HID_ + d];
            float og = gbuf[col][2 * HID_ + d];
            float gg = gbuf[col][3 * HID_ + d];
            float cv = sigmf(fg) * cbuf[d * HP + col] + sigmf(ig) * tanhf_(gg);
            float hv = sigmf(og) * tanhf_(cv);
            cbuf[d * HP + col] = cv;
            hbuf[d * HP + col] = hv;
        }
        __syncthreads();

        if (t < HID_) {
            const int d = t;
            float4 v0 = make_float4(hbuf[d * HP + 0], hbuf[d * HP + 1],
                                    hbuf[d * HP + 2], hbuf[d * HP + 3]);
            float4 v1 = make_float4(hbuf[d * HP + 4], hbuf[d * HP + 5],
                                    hbuf[d * HP + 6], hbuf[d * HP + 7]);
            float* op = out + ((((size_t)b * HID_ + d) * H_) + row) * W_ + w0;
            *reinterpret_cast<float4*>(op)     = v0;
            *reinterpret_cast<float4*>(op + 4) = v1;
        }
    }
}

// ---------------------------------------------------------------------------
extern "C" void kernel_launch(void* const* d_in, const int* in_sizes, int n_in,
                              void* d_out, int out_size)
{
    (void)in_sizes; (void)n_in; (void)out_size;
    const float* x  = (const float*)d_in[0];
    const float* Wi = (const float*)d_in[1];
    const float* bi = (const float*)d_in[2];
    const float* Wh = (const float*)d_in[3];
    const float* bh = (const float*)d_in[4];
    float* out = (float*)d_out;

    static bool attr_set = false;
    if (!attr_set) {
        cudaFuncSetAttribute(i2h_kernel, cudaFuncAttributeMaxDynamicSharedMemorySize, SMEM_I2H);
        attr_set = true;
    }

    prep_kernel<<<HID_, G_>>>(Wh);
    i2h_kernel<<<B_ * 8, 256, SMEM_I2H>>>(x, Wi);
    rec_kernel<<<B_ * (W_ / 8), 512>>>(bi, bh, out);
}

// round 8
// speedup vs baseline: 1.6345x; 1.6345x over previous
#include <cuda_runtime.h>
#include <cuda_bf16.h>
#include <cstdint>

// ---------------------------------------------------------------------------
// RowLSTM: x(16,64,64,64), Wi(512,64,1,3), bi(512), Wh(512,128), bh(512)
// out: (16,128,64,64) fp32
// Phase 1 (i2h): mma.sync bf16 3-pass hi/lo; conv as 3 kw-shifted K=64 GEMMs.
//   All fp32->bf16 splitting done in prep kernels; hot loop = LDS + HMMA only.
// Phase 2 (rec): fp32 scan (R4 structure, coalesced WhT), bias fused.
// ---------------------------------------------------------------------------

#define B_  16
#define C_  64
#define H_  64
#define W_  64
#define HID_ 128
#define G_  512
#define K_  192

static __device__ float    g_i2h[(size_t)H_ * B_ * W_ * G_];   // [h][b][w][g]
static __device__ float    g_WhT[(size_t)HID_ * G_];           // [k][g]
static __device__ uint32_t g_xTh[(size_t)B_ * H_ * 66 * 32];   // [b][h][wp][cq] bf16x2 hi
static __device__ uint32_t g_xTl[(size_t)B_ * H_ * 66 * 32];   // lo
static __device__ uint32_t g_WiFh[49152];                      // [kw][kt][mt][lane][reg]
static __device__ uint32_t g_WiFl[49152];

__device__ __forceinline__ float sigmf(float v) {
    return __fdividef(1.0f, 1.0f + __expf(-v));
}
__device__ __forceinline__ float tanhf_(float v) {
    return __fdividef(2.0f, 1.0f + __expf(-2.0f * v)) - 1.0f;
}
__device__ __forceinline__ uint32_t pkbf(float a, float b) {
    __nv_bfloat162 t = __floats2bfloat162_rn(a, b);
    return *reinterpret_cast<uint32_t*>(&t);
}
__device__ __forceinline__ void split2(float v, float& hi, float& lo) {
    __nv_bfloat16 h = __float2bfloat16_rn(v);
    hi = __bfloat162float(h);
    lo = v - hi;
}
__device__ __forceinline__ void mma_bf16(float d[4], const uint32_t a[4], const uint32_t b[2]) {
    asm volatile(
        "mma.sync.aligned.m16n8k16.row.col.f32.bf16.bf16.f32 "
        "{%0,%1,%2,%3},{%4,%5,%6,%7},{%8,%9},{%0,%1,%2,%3};"
        : "+f"(d[0]), "+f"(d[1]), "+f"(d[2]), "+f"(d[3])
        : "r"(a[0]), "r"(a[1]), "r"(a[2]), "r"(a[3]), "r"(b[0]), "r"(b[1]));
}

// ---------------------------------------------------------------------------
// Prep 0: Wh -> WhT[k][g]
// ---------------------------------------------------------------------------
__global__ void prep_wh(const float* __restrict__ Wh)
{
    int k = blockIdx.x, g = threadIdx.x;
    g_WhT[(size_t)k * G_ + g] = Wh[(size_t)g * HID_ + k];
}

// ---------------------------------------------------------------------------
// Prep 1: x -> xT hi/lo bf16x2, layout [b][h][wp(66)][cq(32)], zero-padded wp ends
// ---------------------------------------------------------------------------
__global__ void __launch_bounds__(256)
prep_x(const float* __restrict__ x)
{
    const int b = blockIdx.x >> 6, h = blockIdx.x & 63;
    const int tid = threadIdx.x;
    __shared__ float xt[64][65];
    for (int idx = tid; idx < 4096; idx += 256) {
        int c = idx >> 6, w = idx & 63;
        xt[c][w] = x[(((size_t)b * C_ + c) * H_ + h) * W_ + w];
    }
    __syncthreads();
    for (int idx = tid; idx < 66 * 32; idx += 256) {
        int wp = idx >> 5, cq = idx & 31, c0 = cq * 2;
        uint32_t vh = 0u, vl = 0u;
        if (wp >= 1 && wp <= 64) {
            int w = wp - 1;
            float ah, al, bh, bl;
            split2(xt[c0][w], ah, al);
            split2(xt[c0 + 1][w], bh, bl);
            vh = pkbf(ah, bh);
            vl = pkbf(al, bl);
        }
        size_t o = (((size_t)b * H_ + h) * 66 + wp) * 32 + cq;
        g_xTh[o] = vh;
        g_xTl[o] = vl;
    }
}

// ---------------------------------------------------------------------------
// Prep 2: Wi -> fragment-linear hi/lo  [kw(3)][kt(4)][mt(32)][lane(32)][reg(4)]
// A frag m16n8k16 row-major: reg0:(grp,2tig) reg1:(grp+8,2tig) reg2:(grp,2tig+8) reg3:(grp+8,2tig+8)
// k index = c within the kw plane: Wi element = Wi[g][c*3+kw]
// ---------------------------------------------------------------------------
__global__ void __launch_bounds__(512)
prep_wif(const float* __restrict__ Wi)
{
    int gid = blockIdx.x * 512 + threadIdx.x;   // < 49152
    int reg = gid & 3, lane = (gid >> 2) & 31, mt = (gid >> 7) & 31;
    int kt = (gid >> 12) & 3, kw = gid >> 14;
    int grp = lane >> 2, tig = lane & 3;
    int g  = mt * 16 + grp + 8 * (reg & 1);
    int c0 = kt * 16 + 2 * tig + 8 * (reg >> 1);
    float a = Wi[(size_t)g * K_ + c0 * 3 + kw];
    float b = Wi[(size_t)g * K_ + (c0 + 1) * 3 + kw];
    float ah, al, bh, bl;
    split2(a, ah, al);
    split2(b, bh, bl);
    g_WiFh[gid] = pkbf(ah, bh);
    g_WiFl[gid] = pkbf(al, bl);
}

// ---------------------------------------------------------------------------
// Kernel A: i2h. Grid 512 = gc(8) x b(16) x ic(4). 256 threads = 8 warps.
// Block tile: 64 gates x 128 spatial (h-pair), 8 h-pair iterations.
// Warp: wg (2 gate 16-tiles) x wn (4 spatial 8-tiles).
// smem: A frags 48KB + union(xs hi/lo 38KB, staging 32KB) = 87168 B -> occ 2.
// ---------------------------------------------------------------------------
#define A_HI  0
#define A_LO  24576
#define XS_HI 49152
#define XS_LO 68160
#define STGB  49152
#define SMEM_I2H 87168

__global__ void __launch_bounds__(256, 2)
i2h_kernel()
{
    extern __shared__ char sm[];
    const int gc = blockIdx.x & 7;
    const int b  = (blockIdx.x >> 3) & 15;
    const int ic = blockIdx.x >> 7;
    const int tid  = threadIdx.x;
    const int lane = tid & 31;
    const int warp = tid >> 5;
    const int wg   = warp >> 2;    // 0..1
    const int wn   = warp & 3;     // 0..3
    const int grp  = lane >> 2;
    const int tig  = lane & 3;

    uint4* ah4 = reinterpret_cast<uint4*>(sm + A_HI);
    uint4* al4 = reinterpret_cast<uint4*>(sm + A_LO);
    const uint4* wfh4 = reinterpret_cast<const uint4*>(g_WiFh);
    const uint4* wfl4 = reinterpret_cast<const uint4*>(g_WiFl);

    // ---- A fragments: copy block's 64-gate slice (mt = gc*4+gt) to smem ----
    for (int idx = tid; idx < 1536; idx += 256) {
        int ln = idx & 31, gt = (idx >> 5) & 3, kt = (idx >> 7) & 3, kw = idx >> 9;
        int src = ((kw * 4 + kt) * 32 + gc * 4 + gt) * 32 + ln;
        int dst = ((kw * 4 + kt) * 4 + gt) * 32 + ln;
        ah4[dst] = wfh4[src];
        al4[dst] = wfl4[src];
    }

    // per-lane B base offsets (bytes within XS arrays), per n-tile
    int nbase[4];
#pragma unroll
    for (int nt2 = 0; nt2 < 4; nt2++) {
        int n = (wn * 4 + nt2) * 8 + grp;
        int hs = n >> 6, w = n & 63;
        nbase[nt2] = hs * 9504 + w * 144;    // (hs*66*72 + w*72) * 2 bytes
    }

    uint32_t* xh = reinterpret_cast<uint32_t*>(sm + XS_HI);
    uint32_t* xl = reinterpret_cast<uint32_t*>(sm + XS_LO);
    float* stg = reinterpret_cast<float*>(sm + STGB);

    for (int i = 0; i < 8; i++) {
        const int it = ic * 8 + i;
        const int h0 = it * 2;
        __syncthreads();   // prior STG readers done (staging overlays xs)

        // ---- xs fill: copy xT slice (h-pair) into smem, row stride 36 u32 ----
        for (int idx = tid; idx < 2 * 66 * 32; idx += 256) {
            int hs = idx >> 11;            // idx / 2112
            int rem = idx - hs * 2112;
            int wp = rem >> 5, cq = rem & 31;
            size_t g = (((size_t)b * H_ + h0 + hs) * 66 + wp) * 32 + cq;
            int d = hs * 2376 + wp * 36 + cq;
            xh[d] = g_xTh[g];
            xl[d] = g_xTl[g];
        }
        __syncthreads();

        // ---- mma: warp tile 32g x 32n, 12 (kw,kt) steps, 3 passes ----
        float d[2][4][4];
#pragma unroll
        for (int a = 0; a < 2; a++)
#pragma unroll
            for (int c = 0; c < 4; c++)
#pragma unroll
                for (int r = 0; r < 4; r++) d[a][c][r] = 0.f;

#pragma unroll
        for (int kk = 0; kk < 12; kk++) {
            const int kw = kk >> 2, kt = kk & 3;
            const int koff = kw * 144 + kt * 32 + tig * 4;

            uint4 ahf[2], alf[2];
#pragma unroll
            for (int gt2 = 0; gt2 < 2; gt2++) {
                int fo = (kk * 4 + wg * 2 + gt2) * 32 + lane;
                ahf[gt2] = ah4[fo];
                alf[gt2] = al4[fo];
            }
            uint32_t bhf[4][2], blf[4][2];
#pragma unroll
            for (int nt2 = 0; nt2 < 4; nt2++) {
                int off = nbase[nt2] + koff;
                bhf[nt2][0] = *reinterpret_cast<const uint32_t*>(sm + XS_HI + off);
                bhf[nt2][1] = *reinterpret_cast<const uint32_t*>(sm + XS_HI + off + 16);
                blf[nt2][0] = *reinterpret_cast<const uint32_t*>(sm + XS_LO + off);
                blf[nt2][1] = *reinterpret_cast<const uint32_t*>(sm + XS_LO + off + 16);
            }
#pragma unroll
            for (int gt2 = 0; gt2 < 2; gt2++)
#pragma unroll
                for (int nt2 = 0; nt2 < 4; nt2++)
                    mma_bf16(d[gt2][nt2], &ahf[gt2].x, bhf[nt2]);
#pragma unroll
            for (int gt2 = 0; gt2 < 2; gt2++)
#pragma unroll
                for (int nt2 = 0; nt2 < 4; nt2++)
                    mma_bf16(d[gt2][nt2], &ahf[gt2].x, blf[nt2]);
#pragma unroll
            for (int gt2 = 0; gt2 < 2; gt2++)
#pragma unroll
                for (int nt2 = 0; nt2 < 4; nt2++)
                    mma_bf16(d[gt2][nt2], &alf[gt2].x, bhf[nt2]);
        }
        __syncthreads();   // mma xs readers done before staging overwrite

        // ---- stage d -> stg[n][g-local(64)] ----
#pragma unroll
        for (int gt2 = 0; gt2 < 2; gt2++) {
            int g0 = (wg * 2 + gt2) * 16 + grp;
#pragma unroll
            for (int nt2 = 0; nt2 < 4; nt2++) {
                int n0 = (wn * 4 + nt2) * 8 + 2 * tig;
                stg[n0 * 64 + g0]           = d[gt2][nt2][0];
                stg[(n0 + 1) * 64 + g0]     = d[gt2][nt2][1];
                stg[n0 * 64 + g0 + 8]       = d[gt2][nt2][2];
                stg[(n0 + 1) * 64 + g0 + 8] = d[gt2][nt2][3];
            }
        }
        __syncthreads();

        // ---- coalesced STG: g_i2h[h][b][w][gc*64 + 0..63] ----
#pragma unroll
        for (int u = 0; u < 8; u++) {
            int idx = tid + u * 256;
            int n = idx >> 4;
            int q4 = idx & 15;
            float4 v = *reinterpret_cast<const float4*>(&stg[n * 64 + q4 * 4]);
            size_t dst = ((size_t)(h0 + (n >> 6)) * B_ + b) * (W_ * G_)
                       + (size_t)(n & 63) * G_ + gc * 64 + q4 * 4;
            *reinterpret_cast<float4*>(&g_i2h[dst]) = v;
        }
    }
}

// ---------------------------------------------------------------------------
// Kernel B: recurrent scan (R4 winner + fused bias, unchanged).
// ---------------------------------------------------------------------------
#define HP 10

__global__ void __launch_bounds__(512, 1)
rec_kernel(const float* __restrict__ bi, const float* __restrict__ bh,
           float* __restrict__ out)
{
    const int b  = blockIdx.x >> 3;
    const int w0 = (blockIdx.x & 7) * 8;
    const int t  = threadIdx.x;
    const int q  = t & 127;
    const int ch = t >> 7;

    __shared__ float hbuf[HID_ * HP];
    __shared__ float cbuf[HID_ * HP];
    __shared__ float gbuf[8][G_];

    for (int p = t; p < HID_ * HP; p += 512) { hbuf[p] = 0.f; cbuf[p] = 0.f; }
    __syncthreads();

    float4 bias4;
    {
        float4 v1 = __ldg(reinterpret_cast<const float4*>(bi) + q);
        float4 v2 = __ldg(reinterpret_cast<const float4*>(bh) + q);
        bias4 = make_float4(v1.x + v2.x, v1.y + v2.y, v1.z + v2.z, v1.w + v2.w);
    }

    const float4* __restrict__ WhT4 = reinterpret_cast<const float4*>(g_WhT);

    for (int row = 0; row < H_; row++) {
        const size_t ibase = ((((size_t)row * B_ + b) * W_) + w0 + 2 * ch) * G_ + 4 * q;
        float4 gv0 = *reinterpret_cast<const float4*>(&g_i2h[ibase]);
        float4 gv1 = *reinterpret_cast<const float4*>(&g_i2h[ibase + G_]);
        gv0.x += bias4.x; gv0.y += bias4.y; gv0.z += bias4.z; gv0.w += bias4.w;
        gv1.x += bias4.x; gv1.y += bias4.y; gv1.z += bias4.z; gv1.w += bias4.w;

        float a00 = 0.f, a10 = 0.f, a20 = 0.f, a30 = 0.f;
        float a01 = 0.f, a11 = 0.f, a21 = 0.f, a31 = 0.f;

#pragma unroll 4
        for (int k = 0; k < HID_; k++) {
            float4 wv = __ldg(&WhT4[(size_t)k * (G_ / 4) + q]);
            float2 hv = *reinterpret_cast<const float2*>(&hbuf[k * HP + 2 * ch]);
            a00 = fmaf(wv.x, hv.x, a00); a01 = fmaf(wv.x, hv.y, a01);
            a10 = fmaf(wv.y, hv.x, a10); a11 = fmaf(wv.y, hv.y, a11);
            a20 = fmaf(wv.z, hv.x, a20); a21 = fmaf(wv.z, hv.y, a21);
            a30 = fmaf(wv.w, hv.x, a30); a31 = fmaf(wv.w, hv.y, a31);
        }

        *reinterpret_cast<float4*>(&gbuf[2 * ch][4 * q]) =
            make_float4(a00 + gv0.x, a10 + gv0.y, a20 + gv0.z, a30 + gv0.w);
        *reinterpret_cast<float4*>(&gbuf[2 * ch + 1][4 * q]) =
            make_float4(a01 + gv1.x, a11 + gv1.y, a21 + gv1.z, a31 + gv1.w);
        __syncthreads();

#pragma unroll
        for (int pp = 0; pp < 2; pp++) {
            int p   = t + pp * 512;
            int col = p >> 7;
            int dd  = p & 127;
            float ig = gbuf[col][dd];
            float fg = gbuf[col][HID_ + dd];
            float og = gbuf[col][2 * HID_ + dd];
            float gg = gbuf[col][3 * HID_ + dd];
            float cv = sigmf(fg) * cbuf[dd * HP + col] + sigmf(ig) * tanhf_(gg);
            float hv = sigmf(og) * tanhf_(cv);
            cbuf[dd * HP + col] = cv;
            hbuf[dd * HP + col] = hv;
        }
        __syncthreads();

        if (t < HID_) {
            const int dd = t;
            float4 v0 = make_float4(hbuf[dd * HP + 0], hbuf[dd * HP + 1],
                                    hbuf[dd * HP + 2], hbuf[dd * HP + 3]);
            float4 v1 = make_float4(hbuf[dd * HP + 4], hbuf[dd * HP + 5],
                                    hbuf[dd * HP + 6], hbuf[dd * HP + 7]);
            float* op = out + ((((size_t)b * HID_ + dd) * H_) + row) * W_ + w0;
            *reinterpret_cast<float4*>(op)     = v0;
            *reinterpret_cast<float4*>(op + 4) = v1;
        }
    }
}

// ---------------------------------------------------------------------------
extern "C" void kernel_launch(void* const* d_in, const int* in_sizes, int n_in,
                              void* d_out, int out_size)
{
    (void)in_sizes; (void)n_in; (void)out_size;
    const float* x  = (const float*)d_in[0];
    const float* Wi = (const float*)d_in[1];
    const float* bi = (const float*)d_in[2];
    const float* Wh = (const float*)d_in[3];
    const float* bh = (const float*)d_in[4];
    float* out = (float*)d_out;

    static bool attr_set = false;
    if (!attr_set) {
        cudaFuncSetAttribute(i2h_kernel, cudaFuncAttributeMaxDynamicSharedMemorySize, SMEM_I2H);
        attr_set = true;
    }

    prep_wh<<<HID_, G_>>>(Wh);
    prep_x<<<B_ * H_, 256>>>(x);
    prep_wif<<<96, 512>>>(Wi);
    i2h_kernel<<<512, 256, SMEM_I2H>>>();
    rec_kernel<<<B_ * (W_ / 8), 512>>>(bi, bh, out);
}

// round 9
// speedup vs baseline: 3.2423x; 1.9836x over previous
#include <cuda_runtime.h>
#include <cuda_bf16.h>
#include <cstdint>

// ---------------------------------------------------------------------------
// RowLSTM: x(16,64,64,64), Wi(512,64,1,3), bi(512), Wh(512,128), bh(512)
// out: (16,128,64,64) fp32
// Phase 1 (i2h): mma.sync bf16 3-pass hi/lo conv-GEMM (R8 winner, unchanged)
// Phase 2 (rec): mma.sync bf16 3-pass hi/lo recurrent GEMM + fp32 pointwise
// ---------------------------------------------------------------------------

#define B_  16
#define C_  64
#define H_  64
#define W_  64
#define HID_ 128
#define G_  512
#define K_  192

static __device__ float    g_i2h[(size_t)H_ * B_ * W_ * G_];   // [h][b][w][g]
static __device__ uint32_t g_xTh[(size_t)B_ * H_ * 66 * 32];   // [b][h][wp][cq] bf16x2 hi
static __device__ uint32_t g_xTl[(size_t)B_ * H_ * 66 * 32];   // lo
static __device__ uint32_t g_WiFh[49152];                      // [kw][kt][mt][lane][reg]
static __device__ uint32_t g_WiFl[49152];
static __device__ uint32_t g_WhFh[32768];                      // [kt(8)][mt(32)][lane(32)][reg(4)]
static __device__ uint32_t g_WhFl[32768];

__device__ __forceinline__ float sigmf(float v) {
    return __fdividef(1.0f, 1.0f + __expf(-v));
}
__device__ __forceinline__ float tanhf_(float v) {
    return __fdividef(2.0f, 1.0f + __expf(-2.0f * v)) - 1.0f;
}
__device__ __forceinline__ uint32_t pkbf(float a, float b) {
    __nv_bfloat162 t = __floats2bfloat162_rn(a, b);
    return *reinterpret_cast<uint32_t*>(&t);
}
__device__ __forceinline__ void split2(float v, float& hi, float& lo) {
    __nv_bfloat16 h = __float2bfloat16_rn(v);
    hi = __bfloat162float(h);
    lo = v - hi;
}
__device__ __forceinline__ void mma_bf16(float d[4], const uint32_t a[4], const uint32_t b[2]) {
    asm volatile(
        "mma.sync.aligned.m16n8k16.row.col.f32.bf16.bf16.f32 "
        "{%0,%1,%2,%3},{%4,%5,%6,%7},{%8,%9},{%0,%1,%2,%3};"
        : "+f"(d[0]), "+f"(d[1]), "+f"(d[2]), "+f"(d[3])
        : "r"(a[0]), "r"(a[1]), "r"(a[2]), "r"(a[3]), "r"(b[0]), "r"(b[1]));
}

// ---------------------------------------------------------------------------
// Prep 1: x -> xT hi/lo bf16x2, layout [b][h][wp(66)][cq(32)], zero-padded ends
// ---------------------------------------------------------------------------
__global__ void __launch_bounds__(256)
prep_x(const float* __restrict__ x)
{
    const int b = blockIdx.x >> 6, h = blockIdx.x & 63;
    const int tid = threadIdx.x;
    __shared__ float xt[64][65];
    for (int idx = tid; idx < 4096; idx += 256) {
        int c = idx >> 6, w = idx & 63;
        xt[c][w] = x[(((size_t)b * C_ + c) * H_ + h) * W_ + w];
    }
    __syncthreads();
    for (int idx = tid; idx < 66 * 32; idx += 256) {
        int wp = idx >> 5, cq = idx & 31, c0 = cq * 2;
        uint32_t vh = 0u, vl = 0u;
        if (wp >= 1 && wp <= 64) {
            int w = wp - 1;
            float ah, al, bh, bl;
            split2(xt[c0][w], ah, al);
            split2(xt[c0 + 1][w], bh, bl);
            vh = pkbf(ah, bh);
            vl = pkbf(al, bl);
        }
        size_t o = (((size_t)b * H_ + h) * 66 + wp) * 32 + cq;
        g_xTh[o] = vh;
        g_xTl[o] = vl;
    }
}

// ---------------------------------------------------------------------------
// Prep 2: Wi -> fragment-linear hi/lo [kw(3)][kt(4)][mt(32)][lane(32)][reg(4)]
// ---------------------------------------------------------------------------
__global__ void __launch_bounds__(512)
prep_wif(const float* __restrict__ Wi)
{
    int gid = blockIdx.x * 512 + threadIdx.x;   // < 49152
    int reg = gid & 3, lane = (gid >> 2) & 31, mt = (gid >> 7) & 31;
    int kt = (gid >> 12) & 3, kw = gid >> 14;
    int grp = lane >> 2, tig = lane & 3;
    int g  = mt * 16 + grp + 8 * (reg & 1);
    int c0 = kt * 16 + 2 * tig + 8 * (reg >> 1);
    float a = Wi[(size_t)g * K_ + c0 * 3 + kw];
    float b = Wi[(size_t)g * K_ + (c0 + 1) * 3 + kw];
    float ah, al, bh, bl;
    split2(a, ah, al);
    split2(b, bh, bl);
    g_WiFh[gid] = pkbf(ah, bh);
    g_WiFl[gid] = pkbf(al, bl);
}

// ---------------------------------------------------------------------------
// Prep 3: Wh -> fragment-linear hi/lo [kt(8)][mt(32)][lane(32)][reg(4)]
// ---------------------------------------------------------------------------
__global__ void __launch_bounds__(512)
prep_whf(const float* __restrict__ Wh)
{
    int gid = blockIdx.x * 512 + threadIdx.x;   // < 32768
    int reg = gid & 3, lane = (gid >> 2) & 31, mt = (gid >> 7) & 31;
    int kt = gid >> 12;
    int grp = lane >> 2, tig = lane & 3;
    int g = mt * 16 + grp + 8 * (reg & 1);
    int k = kt * 16 + 2 * tig + 8 * (reg >> 1);
    float a = Wh[(size_t)g * HID_ + k];
    float b = Wh[(size_t)g * HID_ + k + 1];
    float ah, al, bh, bl;
    split2(a, ah, al);
    split2(b, bh, bl);
    g_WhFh[gid] = pkbf(ah, bh);
    g_WhFl[gid] = pkbf(al, bl);
}

// ---------------------------------------------------------------------------
// Kernel A: i2h (R8 winner, unchanged). Grid 512 = gc(8) x b(16) x ic(4).
// ---------------------------------------------------------------------------
#define A_HI  0
#define A_LO  24576
#define XS_HI 49152
#define XS_LO 68160
#define STGB  49152
#define SMEM_I2H 87168

__global__ void __launch_bounds__(256, 2)
i2h_kernel()
{
    extern __shared__ char sm[];
    const int gc = blockIdx.x & 7;
    const int b  = (blockIdx.x >> 3) & 15;
    const int ic = blockIdx.x >> 7;
    const int tid  = threadIdx.x;
    const int lane = tid & 31;
    const int warp = tid >> 5;
    const int wg   = warp >> 2;
    const int wn   = warp & 3;
    const int grp  = lane >> 2;
    const int tig  = lane & 3;

    uint4* ah4 = reinterpret_cast<uint4*>(sm + A_HI);
    uint4* al4 = reinterpret_cast<uint4*>(sm + A_LO);
    const uint4* wfh4 = reinterpret_cast<const uint4*>(g_WiFh);
    const uint4* wfl4 = reinterpret_cast<const uint4*>(g_WiFl);

    for (int idx = tid; idx < 1536; idx += 256) {
        int ln = idx & 31, gt = (idx >> 5) & 3, kt = (idx >> 7) & 3, kw = idx >> 9;
        int src = ((kw * 4 + kt) * 32 + gc * 4 + gt) * 32 + ln;
        int dst = ((kw * 4 + kt) * 4 + gt) * 32 + ln;
        ah4[dst] = wfh4[src];
        al4[dst] = wfl4[src];
    }

    int nbase[4];
#pragma unroll
    for (int nt2 = 0; nt2 < 4; nt2++) {
        int n = (wn * 4 + nt2) * 8 + grp;
        int hs = n >> 6, w = n & 63;
        nbase[nt2] = hs * 9504 + w * 144;
    }

    uint32_t* xh = reinterpret_cast<uint32_t*>(sm + XS_HI);
    uint32_t* xl = reinterpret_cast<uint32_t*>(sm + XS_LO);
    float* stg = reinterpret_cast<float*>(sm + STGB);

    for (int i = 0; i < 8; i++) {
        const int it = ic * 8 + i;
        const int h0 = it * 2;
        __syncthreads();

        for (int idx = tid; idx < 2 * 66 * 32; idx += 256) {
            int hs = idx >> 11;
            int rem = idx - hs * 2112;
            int wp = rem >> 5, cq = rem & 31;
            size_t g = (((size_t)b * H_ + h0 + hs) * 66 + wp) * 32 + cq;
            int d = hs * 2376 + wp * 36 + cq;
            xh[d] = g_xTh[g];
            xl[d] = g_xTl[g];
        }
        __syncthreads();

        float d[2][4][4];
#pragma unroll
        for (int a = 0; a < 2; a++)
#pragma unroll
            for (int c = 0; c < 4; c++)
#pragma unroll
                for (int r = 0; r < 4; r++) d[a][c][r] = 0.f;

#pragma unroll
        for (int kk = 0; kk < 12; kk++) {
            const int kw = kk >> 2, kt = kk & 3;
            const int koff = kw * 144 + kt * 32 + tig * 4;

            uint4 ahf[2], alf[2];
#pragma unroll
            for (int gt2 = 0; gt2 < 2; gt2++) {
                int fo = (kk * 4 + wg * 2 + gt2) * 32 + lane;
                ahf[gt2] = ah4[fo];
                alf[gt2] = al4[fo];
            }
            uint32_t bhf[4][2], blf[4][2];
#pragma unroll
            for (int nt2 = 0; nt2 < 4; nt2++) {
                int off = nbase[nt2] + koff;
                bhf[nt2][0] = *reinterpret_cast<const uint32_t*>(sm + XS_HI + off);
                bhf[nt2][1] = *reinterpret_cast<const uint32_t*>(sm + XS_HI + off + 16);
                blf[nt2][0] = *reinterpret_cast<const uint32_t*>(sm + XS_LO + off);
                blf[nt2][1] = *reinterpret_cast<const uint32_t*>(sm + XS_LO + off + 16);
            }
#pragma unroll
            for (int gt2 = 0; gt2 < 2; gt2++)
#pragma unroll
                for (int nt2 = 0; nt2 < 4; nt2++)
                    mma_bf16(d[gt2][nt2], &ahf[gt2].x, bhf[nt2]);
#pragma unroll
            for (int gt2 = 0; gt2 < 2; gt2++)
#pragma unroll
                for (int nt2 = 0; nt2 < 4; nt2++)
                    mma_bf16(d[gt2][nt2], &ahf[gt2].x, blf[nt2]);
#pragma unroll
            for (int gt2 = 0; gt2 < 2; gt2++)
#pragma unroll
                for (int nt2 = 0; nt2 < 4; nt2++)
                    mma_bf16(d[gt2][nt2], &alf[gt2].x, bhf[nt2]);
        }
        __syncthreads();

#pragma unroll
        for (int gt2 = 0; gt2 < 2; gt2++) {
            int g0 = (wg * 2 + gt2) * 16 + grp;
#pragma unroll
            for (int nt2 = 0; nt2 < 4; nt2++) {
                int n0 = (wn * 4 + nt2) * 8 + 2 * tig;
                stg[n0 * 64 + g0]           = d[gt2][nt2][0];
                stg[(n0 + 1) * 64 + g0]     = d[gt2][nt2][1];
                stg[n0 * 64 + g0 + 8]       = d[gt2][nt2][2];
                stg[(n0 + 1) * 64 + g0 + 8] = d[gt2][nt2][3];
            }
        }
        __syncthreads();

#pragma unroll
        for (int u = 0; u < 8; u++) {
            int idx = tid + u * 256;
            int n = idx >> 4;
            int q4 = idx & 15;
            float4 v = *reinterpret_cast<const float4*>(&stg[n * 64 + q4 * 4]);
            size_t dst = ((size_t)(h0 + (n >> 6)) * B_ + b) * (W_ * G_)
                       + (size_t)(n & 63) * G_ + gc * 64 + q4 * 4;
            *reinterpret_cast<float4*>(&g_i2h[dst]) = v;
        }
    }
}

// ---------------------------------------------------------------------------
// Kernel B: recurrent scan via mma. 128 blocks = (b, w-group of 8), 512 thr.
// Per row: gates[512x8] = Wh[512x128] . h[128x8] as 32 mt x 8 kt m16n8k16,
// 3-pass hi/lo. 16 warps x 2 mt each. h kept as bf16 hi/lo in smem (written
// by pointwise); c in registers; gbuf padded 516 for conflict-free D stores.
// ---------------------------------------------------------------------------
#define GBS 516   // gbuf row stride (floats)
#define HBS 136   // h bf16 row stride (bf16 units) = 272 B
#define HP  10    // hfp row stride

__global__ void __launch_bounds__(512, 1)
rec_kernel(const float* __restrict__ bi, const float* __restrict__ bh,
           float* __restrict__ out)
{
    const int b  = blockIdx.x >> 3;
    const int w0 = (blockIdx.x & 7) * 8;
    const int t  = threadIdx.x;
    const int lane = t & 31;
    const int warp = t >> 5;        // 0..15
    const int grp  = lane >> 2;
    const int tig  = lane & 3;

    __shared__ __nv_bfloat16 hbh[8 * HBS];   // [col][k] hi
    __shared__ __nv_bfloat16 hbl[8 * HBS];   // lo
    __shared__ float hfp[HID_ * HP];         // [d][col] fp32 (out staging)
    __shared__ float gbuf[8 * GBS];          // [col][gate]

    for (int p = t; p < 8 * HBS; p += 512) {
        hbh[p] = __float2bfloat16(0.f);
        hbl[p] = __float2bfloat16(0.f);
    }
    __syncthreads();

    // pointwise-fixed bias: thread handles p = t and t+512 -> (col,d)
    float bias_i[2], bias_f[2], bias_o[2], bias_g[2];
#pragma unroll
    for (int pp = 0; pp < 2; pp++) {
        int d = (t + pp * 512) & 127;
        bias_i[pp] = bi[d] + bh[d];
        bias_f[pp] = bi[HID_ + d] + bh[HID_ + d];
        bias_o[pp] = bi[2 * HID_ + d] + bh[2 * HID_ + d];
        bias_g[pp] = bi[3 * HID_ + d] + bh[3 * HID_ + d];
    }
    float creg[2] = {0.f, 0.f};

    const uint4* whfh = reinterpret_cast<const uint4*>(g_WhFh);
    const uint4* whfl = reinterpret_cast<const uint4*>(g_WhFl);
    const int mt0 = warp * 2;

    // B-fragment byte offsets (within hbh/hbl): n = grp, k = kt*16 + 2tig
    const int bofs = grp * (HBS * 2) + tig * 4;

    for (int row = 0; row < H_; row++) {
        // ---- load B fragments (h) from smem: conflict-free ----
        uint32_t bhf[8][2], blf[8][2];
#pragma unroll
        for (int kt = 0; kt < 8; kt++) {
            const char* ph = reinterpret_cast<const char*>(hbh) + bofs + kt * 32;
            const char* pl = reinterpret_cast<const char*>(hbl) + bofs + kt * 32;
            bhf[kt][0] = *reinterpret_cast<const uint32_t*>(ph);
            bhf[kt][1] = *reinterpret_cast<const uint32_t*>(ph + 16);
            blf[kt][0] = *reinterpret_cast<const uint32_t*>(pl);
            blf[kt][1] = *reinterpret_cast<const uint32_t*>(pl + 16);
        }

        // ---- mma: 2 mt x 8 kt x 3 passes ----
        float d0[4] = {0.f, 0.f, 0.f, 0.f};
        float d1[4] = {0.f, 0.f, 0.f, 0.f};
#pragma unroll
        for (int kt = 0; kt < 8; kt++) {
            uint4 ah0 = whfh[(kt * 32 + mt0) * 32 + lane];
            uint4 al0 = whfl[(kt * 32 + mt0) * 32 + lane];
            uint4 ah1 = whfh[(kt * 32 + mt0 + 1) * 32 + lane];
            uint4 al1 = whfl[(kt * 32 + mt0 + 1) * 32 + lane];
            mma_bf16(d0, &ah0.x, bhf[kt]);
            mma_bf16(d0, &ah0.x, blf[kt]);
            mma_bf16(d0, &al0.x, bhf[kt]);
            mma_bf16(d1, &ah1.x, bhf[kt]);
            mma_bf16(d1, &ah1.x, blf[kt]);
            mma_bf16(d1, &al1.x, bhf[kt]);
        }

        // ---- D -> gbuf[col][gate], conflict-free via GBS=516 ----
        {
            int g0 = mt0 * 16 + grp;
            gbuf[(2 * tig) * GBS + g0]          = d0[0];
            gbuf[(2 * tig + 1) * GBS + g0]      = d0[1];
            gbuf[(2 * tig) * GBS + g0 + 8]      = d0[2];
            gbuf[(2 * tig + 1) * GBS + g0 + 8]  = d0[3];
            int g1 = g0 + 16;
            gbuf[(2 * tig) * GBS + g1]          = d1[0];
            gbuf[(2 * tig + 1) * GBS + g1]      = d1[1];
            gbuf[(2 * tig) * GBS + g1 + 8]      = d1[2];
            gbuf[(2 * tig + 1) * GBS + g1 + 8]  = d1[3];
        }
        __syncthreads();

        // ---- pointwise: 1024 (col,d) pairs / 512 threads, c in regs ----
#pragma unroll
        for (int pp = 0; pp < 2; pp++) {
            int p   = t + pp * 512;
            int col = p >> 7;
            int d   = p & 127;
            const float* gb = &gbuf[col * GBS];
            const float* iv = &g_i2h[((((size_t)row * B_ + b) * W_) + w0 + col) * G_ + d];
            float ig = gb[d]            + iv[0]       + bias_i[pp];
            float fg = gb[HID_ + d]     + iv[HID_]    + bias_f[pp];
            float og = gb[2 * HID_ + d] + iv[2 * HID_]+ bias_o[pp];
            float gg = gb[3 * HID_ + d] + iv[3 * HID_]+ bias_g[pp];
            float cv = sigmf(fg) * creg[pp] + sigmf(ig) * tanhf_(gg);
            float hv = sigmf(og) * tanhf_(cv);
            creg[pp] = cv;
            hfp[d * HP + col] = hv;
            float hh, hl;
            split2(hv, hh, hl);
            hbh[col * HBS + d] = __float2bfloat16(hh);
            hbl[col * HBS + d] = __float2bfloat16(hl);
        }
        __syncthreads();

        // ---- out write: out[b][d][row][w0..w0+8) ----
        if (t < HID_) {
            const int d = t;
            float4 v0 = make_float4(hfp[d * HP + 0], hfp[d * HP + 1],
                                    hfp[d * HP + 2], hfp[d * HP + 3]);
            float4 v1 = make_float4(hfp[d * HP + 4], hfp[d * HP + 5],
                                    hfp[d * HP + 6], hfp[d * HP + 7]);
            float* op = out + ((((size_t)b * HID_ + d) * H_) + row) * W_ + w0;
            *reinterpret_cast<float4*>(op)     = v0;
            *reinterpret_cast<float4*>(op + 4) = v1;
        }
        // no barrier: next mma reads hbh (written pre-sync); next gbuf STS
        // happens after those reads in program order per-thread, and gbuf
        // consumers synced above.
        __syncthreads();
    }
}

// ---------------------------------------------------------------------------
extern "C" void kernel_launch(void* const* d_in, const int* in_sizes, int n_in,
                              void* d_out, int out_size)
{
    (void)in_sizes; (void)n_in; (void)out_size;
    const float* x  = (const float*)d_in[0];
    const float* Wi = (const float*)d_in[1];
    const float* bi = (const float*)d_in[2];
    const float* Wh = (const float*)d_in[3];
    const float* bh = (const float*)d_in[4];
    float* out = (float*)d_out;

    static bool attr_set = false;
    if (!attr_set) {
        cudaFuncSetAttribute(i2h_kernel, cudaFuncAttributeMaxDynamicSharedMemorySize, SMEM_I2H);
        attr_set = true;
    }

    prep_x<<<B_ * H_, 256>>>(x);
    prep_wif<<<96, 512>>>(Wi);
    prep_whf<<<64, 512>>>(Wh);
    i2h_kernel<<<512, 256, SMEM_I2H>>>();
    rec_kernel<<<B_ * (W_ / 8), 512>>>(bi, bh, out);
}

// round 10
// speedup vs baseline: 3.9546x; 1.2197x over previous
#include <cuda_runtime.h>
#include <cuda_bf16.h>
#include <cstdint>

// ---------------------------------------------------------------------------
// RowLSTM: x(16,64,64,64), Wi(512,64,1,3), bi(512), Wh(512,128), bh(512)
// out: (16,128,64,64) fp32
// Phase 1 (i2h): mma.sync bf16 3-pass hi/lo conv-GEMM (R8 winner, unchanged)
// Phase 2 (rec): mma.sync bf16 2-pass (Wh_hi x {h_hi, h_lo}) + fp32 pointwise
//   Wh-lo pass dropped: error ~2e-4 << 1e-3, and the Wh-hi fragment set
//   (128 KB) now fits L1 -> per-row LDG delivery halves and L2 traffic ~0.
// ---------------------------------------------------------------------------

#define B_  16
#define C_  64
#define H_  64
#define W_  64
#define HID_ 128
#define G_  512
#define K_  192

static __device__ float    g_i2h[(size_t)H_ * B_ * W_ * G_];   // [h][b][w][g]
static __device__ uint32_t g_xTh[(size_t)B_ * H_ * 66 * 32];   // [b][h][wp][cq] bf16x2 hi
static __device__ uint32_t g_xTl[(size_t)B_ * H_ * 66 * 32];   // lo
static __device__ uint32_t g_WiFh[49152];                      // [kw][kt][mt][lane][reg]
static __device__ uint32_t g_WiFl[49152];
static __device__ uint32_t g_WhFh[32768];                      // [kt(8)][mt(32)][lane(32)][reg(4)]

__device__ __forceinline__ float sigmf(float v) {
    return __fdividef(1.0f, 1.0f + __expf(-v));
}
__device__ __forceinline__ float tanhf_(float v) {
    return __fdividef(2.0f, 1.0f + __expf(-2.0f * v)) - 1.0f;
}
__device__ __forceinline__ uint32_t pkbf(float a, float b) {
    __nv_bfloat162 t = __floats2bfloat162_rn(a, b);
    return *reinterpret_cast<uint32_t*>(&t);
}
__device__ __forceinline__ void split2(float v, float& hi, float& lo) {
    __nv_bfloat16 h = __float2bfloat16_rn(v);
    hi = __bfloat162float(h);
    lo = v - hi;
}
__device__ __forceinline__ void mma_bf16(float d[4], const uint32_t a[4], const uint32_t b[2]) {
    asm volatile(
        "mma.sync.aligned.m16n8k16.row.col.f32.bf16.bf16.f32 "
        "{%0,%1,%2,%3},{%4,%5,%6,%7},{%8,%9},{%0,%1,%2,%3};"
        : "+f"(d[0]), "+f"(d[1]), "+f"(d[2]), "+f"(d[3])
        : "r"(a[0]), "r"(a[1]), "r"(a[2]), "r"(a[3]), "r"(b[0]), "r"(b[1]));
}

// ---------------------------------------------------------------------------
// Prep 1: x -> xT hi/lo bf16x2, layout [b][h][wp(66)][cq(32)], zero-padded ends
// ---------------------------------------------------------------------------
__global__ void __launch_bounds__(256)
prep_x(const float* __restrict__ x)
{
    const int b = blockIdx.x >> 6, h = blockIdx.x & 63;
    const int tid = threadIdx.x;
    __shared__ float xt[64][65];
    for (int idx = tid; idx < 4096; idx += 256) {
        int c = idx >> 6, w = idx & 63;
        xt[c][w] = x[(((size_t)b * C_ + c) * H_ + h) * W_ + w];
    }
    __syncthreads();
    for (int idx = tid; idx < 66 * 32; idx += 256) {
        int wp = idx >> 5, cq = idx & 31, c0 = cq * 2;
        uint32_t vh = 0u, vl = 0u;
        if (wp >= 1 && wp <= 64) {
            int w = wp - 1;
            float ah, al, bh, bl;
            split2(xt[c0][w], ah, al);
            split2(xt[c0 + 1][w], bh, bl);
            vh = pkbf(ah, bh);
            vl = pkbf(al, bl);
        }
        size_t o = (((size_t)b * H_ + h) * 66 + wp) * 32 + cq;
        g_xTh[o] = vh;
        g_xTl[o] = vl;
    }
}

// ---------------------------------------------------------------------------
// Prep 2: Wi -> fragment-linear hi/lo [kw(3)][kt(4)][mt(32)][lane(32)][reg(4)]
// ---------------------------------------------------------------------------
__global__ void __launch_bounds__(512)
prep_wif(const float* __restrict__ Wi)
{
    int gid = blockIdx.x * 512 + threadIdx.x;   // < 49152
    int reg = gid & 3, lane = (gid >> 2) & 31, mt = (gid >> 7) & 31;
    int kt = (gid >> 12) & 3, kw = gid >> 14;
    int grp = lane >> 2, tig = lane & 3;
    int g  = mt * 16 + grp + 8 * (reg & 1);
    int c0 = kt * 16 + 2 * tig + 8 * (reg >> 1);
    float a = Wi[(size_t)g * K_ + c0 * 3 + kw];
    float b = Wi[(size_t)g * K_ + (c0 + 1) * 3 + kw];
    float ah, al, bh, bl;
    split2(a, ah, al);
    split2(b, bh, bl);
    g_WiFh[gid] = pkbf(ah, bh);
    g_WiFl[gid] = pkbf(al, bl);
}

// ---------------------------------------------------------------------------
// Prep 3: Wh -> fragment-linear hi only [kt(8)][mt(32)][lane(32)][reg(4)]
// ---------------------------------------------------------------------------
__global__ void __launch_bounds__(512)
prep_whf(const float* __restrict__ Wh)
{
    int gid = blockIdx.x * 512 + threadIdx.x;   // < 32768
    int reg = gid & 3, lane = (gid >> 2) & 31, mt = (gid >> 7) & 31;
    int kt = gid >> 12;
    int grp = lane >> 2, tig = lane & 3;
    int g = mt * 16 + grp + 8 * (reg & 1);
    int k = kt * 16 + 2 * tig + 8 * (reg >> 1);
    float a = Wh[(size_t)g * HID_ + k];
    float b = Wh[(size_t)g * HID_ + k + 1];
    g_WhFh[gid] = pkbf(__bfloat162float(__float2bfloat16_rn(a)),
                       __bfloat162float(__float2bfloat16_rn(b)));
}

// ---------------------------------------------------------------------------
// Kernel A: i2h (R8 winner, unchanged). Grid 512 = gc(8) x b(16) x ic(4).
// ---------------------------------------------------------------------------
#define A_HI  0
#define A_LO  24576
#define XS_HI 49152
#define XS_LO 68160
#define STGB  49152
#define SMEM_I2H 87168

__global__ void __launch_bounds__(256, 2)
i2h_kernel()
{
    extern __shared__ char sm[];
    const int gc = blockIdx.x & 7;
    const int b  = (blockIdx.x >> 3) & 15;
    const int ic = blockIdx.x >> 7;
    const int tid  = threadIdx.x;
    const int lane = tid & 31;
    const int warp = tid >> 5;
    const int wg   = warp >> 2;
    const int wn   = warp & 3;
    const int grp  = lane >> 2;
    const int tig  = lane & 3;

    uint4* ah4 = reinterpret_cast<uint4*>(sm + A_HI);
    uint4* al4 = reinterpret_cast<uint4*>(sm + A_LO);
    const uint4* wfh4 = reinterpret_cast<const uint4*>(g_WiFh);
    const uint4* wfl4 = reinterpret_cast<const uint4*>(g_WiFl);

    for (int idx = tid; idx < 1536; idx += 256) {
        int ln = idx & 31, gt = (idx >> 5) & 3, kt = (idx >> 7) & 3, kw = idx >> 9;
        int src = ((kw * 4 + kt) * 32 + gc * 4 + gt) * 32 + ln;
        int dst = ((kw * 4 + kt) * 4 + gt) * 32 + ln;
        ah4[dst] = wfh4[src];
        al4[dst] = wfl4[src];
    }

    int nbase[4];
#pragma unroll
    for (int nt2 = 0; nt2 < 4; nt2++) {
        int n = (wn * 4 + nt2) * 8 + grp;
        int hs = n >> 6, w = n & 63;
        nbase[nt2] = hs * 9504 + w * 144;
    }

    uint32_t* xh = reinterpret_cast<uint32_t*>(sm + XS_HI);
    uint32_t* xl = reinterpret_cast<uint32_t*>(sm + XS_LO);
    float* stg = reinterpret_cast<float*>(sm + STGB);

    for (int i = 0; i < 8; i++) {
        const int it = ic * 8 + i;
        const int h0 = it * 2;
        __syncthreads();

        for (int idx = tid; idx < 2 * 66 * 32; idx += 256) {
            int hs = idx >> 11;
            int rem = idx - hs * 2112;
            int wp = rem >> 5, cq = rem & 31;
            size_t g = (((size_t)b * H_ + h0 + hs) * 66 + wp) * 32 + cq;
            int d = hs * 2376 + wp * 36 + cq;
            xh[d] = g_xTh[g];
            xl[d] = g_xTl[g];
        }
        __syncthreads();

        float d[2][4][4];
#pragma unroll
        for (int a = 0; a < 2; a++)
#pragma unroll
            for (int c = 0; c < 4; c++)
#pragma unroll
                for (int r = 0; r < 4; r++) d[a][c][r] = 0.f;

#pragma unroll
        for (int kk = 0; kk < 12; kk++) {
            const int kw = kk >> 2, kt = kk & 3;
            const int koff = kw * 144 + kt * 32 + tig * 4;

            uint4 ahf[2], alf[2];
#pragma unroll
            for (int gt2 = 0; gt2 < 2; gt2++) {
                int fo = (kk * 4 + wg * 2 + gt2) * 32 + lane;
                ahf[gt2] = ah4[fo];
                alf[gt2] = al4[fo];
            }
            uint32_t bhf[4][2], blf[4][2];
#pragma unroll
            for (int nt2 = 0; nt2 < 4; nt2++) {
                int off = nbase[nt2] + koff;
                bhf[nt2][0] = *reinterpret_cast<const uint32_t*>(sm + XS_HI + off);
                bhf[nt2][1] = *reinterpret_cast<const uint32_t*>(sm + XS_HI + off + 16);
                blf[nt2][0] = *reinterpret_cast<const uint32_t*>(sm + XS_LO + off);
                blf[nt2][1] = *reinterpret_cast<const uint32_t*>(sm + XS_LO + off + 16);
            }
#pragma unroll
            for (int gt2 = 0; gt2 < 2; gt2++)
#pragma unroll
                for (int nt2 = 0; nt2 < 4; nt2++)
                    mma_bf16(d[gt2][nt2], &ahf[gt2].x, bhf[nt2]);
#pragma unroll
            for (int gt2 = 0; gt2 < 2; gt2++)
#pragma unroll
                for (int nt2 = 0; nt2 < 4; nt2++)
                    mma_bf16(d[gt2][nt2], &ahf[gt2].x, blf[nt2]);
#pragma unroll
            for (int gt2 = 0; gt2 < 2; gt2++)
#pragma unroll
                for (int nt2 = 0; nt2 < 4; nt2++)
                    mma_bf16(d[gt2][nt2], &alf[gt2].x, bhf[nt2]);
        }
        __syncthreads();

#pragma unroll
        for (int gt2 = 0; gt2 < 2; gt2++) {
            int g0 = (wg * 2 + gt2) * 16 + grp;
#pragma unroll
            for (int nt2 = 0; nt2 < 4; nt2++) {
                int n0 = (wn * 4 + nt2) * 8 + 2 * tig;
                stg[n0 * 64 + g0]           = d[gt2][nt2][0];
                stg[(n0 + 1) * 64 + g0]     = d[gt2][nt2][1];
                stg[n0 * 64 + g0 + 8]       = d[gt2][nt2][2];
                stg[(n0 + 1) * 64 + g0 + 8] = d[gt2][nt2][3];
            }
        }
        __syncthreads();

#pragma unroll
        for (int u = 0; u < 8; u++) {
            int idx = tid + u * 256;
            int n = idx >> 4;
            int q4 = idx & 15;
            float4 v = *reinterpret_cast<const float4*>(&stg[n * 64 + q4 * 4]);
            size_t dst = ((size_t)(h0 + (n >> 6)) * B_ + b) * (W_ * G_)
                       + (size_t)(n & 63) * G_ + gc * 64 + q4 * 4;
            *reinterpret_cast<float4*>(&g_i2h[dst]) = v;
        }
    }
}

// ---------------------------------------------------------------------------
// Kernel B: recurrent scan via mma, 2-pass. 128 blocks = (b, w8), 512 thr.
// Per row: gates = Wh_hi . (h_hi + h_lo); Wh-hi fragments (128 KB) L1-resident.
// ---------------------------------------------------------------------------
#define GBS 516   // gbuf row stride (floats)
#define HBS 136   // h bf16 row stride (bf16 units) = 272 B
#define HP  10    // hfp row stride

__global__ void __launch_bounds__(512, 1)
rec_kernel(const float* __restrict__ bi, const float* __restrict__ bh,
           float* __restrict__ out)
{
    const int b  = blockIdx.x >> 3;
    const int w0 = (blockIdx.x & 7) * 8;
    const int t  = threadIdx.x;
    const int lane = t & 31;
    const int warp = t >> 5;        // 0..15
    const int grp  = lane >> 2;
    const int tig  = lane & 3;

    __shared__ __nv_bfloat16 hbh[8 * HBS];   // [col][k] hi
    __shared__ __nv_bfloat16 hbl[8 * HBS];   // lo
    __shared__ float hfp[HID_ * HP];         // [d][col] fp32 (out staging)
    __shared__ float gbuf[8 * GBS];          // [col][gate]

    for (int p = t; p < 8 * HBS; p += 512) {
        hbh[p] = __float2bfloat16(0.f);
        hbl[p] = __float2bfloat16(0.f);
    }
    __syncthreads();

    float bias_i[2], bias_f[2], bias_o[2], bias_g[2];
#pragma unroll
    for (int pp = 0; pp < 2; pp++) {
        int d = (t + pp * 512) & 127;
        bias_i[pp] = bi[d] + bh[d];
        bias_f[pp] = bi[HID_ + d] + bh[HID_ + d];
        bias_o[pp] = bi[2 * HID_ + d] + bh[2 * HID_ + d];
        bias_g[pp] = bi[3 * HID_ + d] + bh[3 * HID_ + d];
    }
    float creg[2] = {0.f, 0.f};

    const uint4* whfh = reinterpret_cast<const uint4*>(g_WhFh);
    const int mt0 = warp * 2;
    const int bofs = grp * (HBS * 2) + tig * 4;

    for (int row = 0; row < H_; row++) {
        // ---- load B fragments (h hi/lo) from smem ----
        uint32_t bhf[8][2], blf[8][2];
#pragma unroll
        for (int kt = 0; kt < 8; kt++) {
            const char* ph = reinterpret_cast<const char*>(hbh) + bofs + kt * 32;
            const char* pl = reinterpret_cast<const char*>(hbl) + bofs + kt * 32;
            bhf[kt][0] = *reinterpret_cast<const uint32_t*>(ph);
            bhf[kt][1] = *reinterpret_cast<const uint32_t*>(ph + 16);
            blf[kt][0] = *reinterpret_cast<const uint32_t*>(pl);
            blf[kt][1] = *reinterpret_cast<const uint32_t*>(pl + 16);
        }

        // ---- mma: 2 mt x 8 kt x 2 passes (Wh-hi only) ----
        float d0[4] = {0.f, 0.f, 0.f, 0.f};
        float d1[4] = {0.f, 0.f, 0.f, 0.f};
#pragma unroll
        for (int kt = 0; kt < 8; kt++) {
            uint4 ah0 = __ldg(&whfh[(kt * 32 + mt0) * 32 + lane]);
            uint4 ah1 = __ldg(&whfh[(kt * 32 + mt0 + 1) * 32 + lane]);
            mma_bf16(d0, &ah0.x, bhf[kt]);
            mma_bf16(d0, &ah0.x, blf[kt]);
            mma_bf16(d1, &ah1.x, bhf[kt]);
            mma_bf16(d1, &ah1.x, blf[kt]);
        }

        // ---- D -> gbuf[col][gate] ----
        {
            int g0 = mt0 * 16 + grp;
            gbuf[(2 * tig) * GBS + g0]          = d0[0];
            gbuf[(2 * tig + 1) * GBS + g0]      = d0[1];
            gbuf[(2 * tig) * GBS + g0 + 8]      = d0[2];
            gbuf[(2 * tig + 1) * GBS + g0 + 8]  = d0[3];
            int g1 = g0 + 16;
            gbuf[(2 * tig) * GBS + g1]          = d1[0];
            gbuf[(2 * tig + 1) * GBS + g1]      = d1[1];
            gbuf[(2 * tig) * GBS + g1 + 8]      = d1[2];
            gbuf[(2 * tig + 1) * GBS + g1 + 8]  = d1[3];
        }
        __syncthreads();

        // ---- pointwise: 1024 (col,d) pairs / 512 threads, c in regs ----
#pragma unroll
        for (int pp = 0; pp < 2; pp++) {
            int p   = t + pp * 512;
            int col = p >> 7;
            int d   = p & 127;
            const float* gb = &gbuf[col * GBS];
            const float* iv = &g_i2h[((((size_t)row * B_ + b) * W_) + w0 + col) * G_ + d];
            float ig = gb[d]            + iv[0]        + bias_i[pp];
            float fg = gb[HID_ + d]     + iv[HID_]     + bias_f[pp];
            float og = gb[2 * HID_ + d] + iv[2 * HID_] + bias_o[pp];
            float gg = gb[3 * HID_ + d] + iv[3 * HID_] + bias_g[pp];
            float cv = sigmf(fg) * creg[pp] + sigmf(ig) * tanhf_(gg);
            float hv = sigmf(og) * tanhf_(cv);
            creg[pp] = cv;
            hfp[d * HP + col] = hv;
            float hh, hl;
            split2(hv, hh, hl);
            hbh[col * HBS + d] = __float2bfloat16(hh);
            hbl[col * HBS + d] = __float2bfloat16(hl);
        }
        __syncthreads();

        // ---- out write: out[b][d][row][w0..w0+8) ----
        if (t < HID_) {
            const int d = t;
            float4 v0 = make_float4(hfp[d * HP + 0], hfp[d * HP + 1],
                                    hfp[d * HP + 2], hfp[d * HP + 3]);
            float4 v1 = make_float4(hfp[d * HP + 4], hfp[d * HP + 5],
                                    hfp[d * HP + 6], hfp[d * HP + 7]);
            float* op = out + ((((size_t)b * HID_ + d) * H_) + row) * W_ + w0;
            *reinterpret_cast<float4*>(op)     = v0;
            *reinterpret_cast<float4*>(op + 4) = v1;
        }
        __syncthreads();
    }
}

// ---------------------------------------------------------------------------
extern "C" void kernel_launch(void* const* d_in, const int* in_sizes, int n_in,
                              void* d_out, int out_size)
{
    (void)in_sizes; (void)n_in; (void)out_size;
    const float* x  = (const float*)d_in[0];
    const float* Wi = (const float*)d_in[1];
    const float* bi = (const float*)d_in[2];
    const float* Wh = (const float*)d_in[3];
    const float* bh = (const float*)d_in[4];
    float* out = (float*)d_out;

    static bool attr_set = false;
    if (!attr_set) {
        cudaFuncSetAttribute(i2h_kernel, cudaFuncAttributeMaxDynamicSharedMemorySize, SMEM_I2H);
        attr_set = true;
    }

    prep_x<<<B_ * H_, 256>>>(x);
    prep_wif<<<96, 512>>>(Wi);
    prep_whf<<<64, 512>>>(Wh);
    i2h_kernel<<<512, 256, SMEM_I2H>>>();
    rec_kernel<<<B_ * (W_ / 8), 512>>>(bi, bh, out);
}

// round 11
// speedup vs baseline: 4.3140x; 1.0909x over previous
#include <cuda_runtime.h>
#include <cuda_bf16.h>
#include <cstdint>

// ---------------------------------------------------------------------------
// RowLSTM: x(16,64,64,64), Wi(512,64,1,3), bi(512), Wh(512,128), bh(512)
// out: (16,128,64,64) fp32
// Phase 1 (i2h): mma.sync bf16 3-pass hi/lo conv-GEMM (R8 winner, unchanged)
// Phase 2 (rec): mma.sync bf16 2-pass; Wh fragments REGISTER-RESIDENT
//   (64 regs/thread, loaded once) -> zero weight traffic in the row loop.
// ---------------------------------------------------------------------------

#define B_  16
#define C_  64
#define H_  64
#define W_  64
#define HID_ 128
#define G_  512
#define K_  192

static __device__ float    g_i2h[(size_t)H_ * B_ * W_ * G_];   // [h][b][w][g]
static __device__ uint32_t g_xTh[(size_t)B_ * H_ * 66 * 32];   // [b][h][wp][cq] bf16x2 hi
static __device__ uint32_t g_xTl[(size_t)B_ * H_ * 66 * 32];   // lo
static __device__ uint32_t g_WiFh[49152];                      // [kw][kt][mt][lane][reg]
static __device__ uint32_t g_WiFl[49152];
static __device__ uint32_t g_WhFh[32768];                      // [kt(8)][mt(32)][lane(32)][reg(4)]

__device__ __forceinline__ float sigmf(float v) {
    return __fdividef(1.0f, 1.0f + __expf(-v));
}
__device__ __forceinline__ float tanhf_(float v) {
    return __fdividef(2.0f, 1.0f + __expf(-2.0f * v)) - 1.0f;
}
__device__ __forceinline__ uint32_t pkbf(float a, float b) {
    __nv_bfloat162 t = __floats2bfloat162_rn(a, b);
    return *reinterpret_cast<uint32_t*>(&t);
}
__device__ __forceinline__ void split2(float v, float& hi, float& lo) {
    __nv_bfloat16 h = __float2bfloat16_rn(v);
    hi = __bfloat162float(h);
    lo = v - hi;
}
__device__ __forceinline__ void mma_bf16(float d[4], const uint32_t a[4], const uint32_t b[2]) {
    asm volatile(
        "mma.sync.aligned.m16n8k16.row.col.f32.bf16.bf16.f32 "
        "{%0,%1,%2,%3},{%4,%5,%6,%7},{%8,%9},{%0,%1,%2,%3};"
        : "+f"(d[0]), "+f"(d[1]), "+f"(d[2]), "+f"(d[3])
        : "r"(a[0]), "r"(a[1]), "r"(a[2]), "r"(a[3]), "r"(b[0]), "r"(b[1]));
}

// ---------------------------------------------------------------------------
// Prep 1: x -> xT hi/lo bf16x2, layout [b][h][wp(66)][cq(32)], zero-padded ends
// ---------------------------------------------------------------------------
__global__ void __launch_bounds__(256)
prep_x(const float* __restrict__ x)
{
    const int b = blockIdx.x >> 6, h = blockIdx.x & 63;
    const int tid = threadIdx.x;
    __shared__ float xt[64][65];
    for (int idx = tid; idx < 4096; idx += 256) {
        int c = idx >> 6, w = idx & 63;
        xt[c][w] = x[(((size_t)b * C_ + c) * H_ + h) * W_ + w];
    }
    __syncthreads();
    for (int idx = tid; idx < 66 * 32; idx += 256) {
        int wp = idx >> 5, cq = idx & 31, c0 = cq * 2;
        uint32_t vh = 0u, vl = 0u;
        if (wp >= 1 && wp <= 64) {
            int w = wp - 1;
            float ah, al, bh, bl;
            split2(xt[c0][w], ah, al);
            split2(xt[c0 + 1][w], bh, bl);
            vh = pkbf(ah, bh);
            vl = pkbf(al, bl);
        }
        size_t o = (((size_t)b * H_ + h) * 66 + wp) * 32 + cq;
        g_xTh[o] = vh;
        g_xTl[o] = vl;
    }
}

// ---------------------------------------------------------------------------
// Prep 2: Wi -> fragment-linear hi/lo [kw(3)][kt(4)][mt(32)][lane(32)][reg(4)]
// ---------------------------------------------------------------------------
__global__ void __launch_bounds__(512)
prep_wif(const float* __restrict__ Wi)
{
    int gid = blockIdx.x * 512 + threadIdx.x;   // < 49152
    int reg = gid & 3, lane = (gid >> 2) & 31, mt = (gid >> 7) & 31;
    int kt = (gid >> 12) & 3, kw = gid >> 14;
    int grp = lane >> 2, tig = lane & 3;
    int g  = mt * 16 + grp + 8 * (reg & 1);
    int c0 = kt * 16 + 2 * tig + 8 * (reg >> 1);
    float a = Wi[(size_t)g * K_ + c0 * 3 + kw];
    float b = Wi[(size_t)g * K_ + (c0 + 1) * 3 + kw];
    float ah, al, bh, bl;
    split2(a, ah, al);
    split2(b, bh, bl);
    g_WiFh[gid] = pkbf(ah, bh);
    g_WiFl[gid] = pkbf(al, bl);
}

// ---------------------------------------------------------------------------
// Prep 3: Wh -> fragment-linear hi only [kt(8)][mt(32)][lane(32)][reg(4)]
// ---------------------------------------------------------------------------
__global__ void __launch_bounds__(512)
prep_whf(const float* __restrict__ Wh)
{
    int gid = blockIdx.x * 512 + threadIdx.x;   // < 32768
    int reg = gid & 3, lane = (gid >> 2) & 31, mt = (gid >> 7) & 31;
    int kt = gid >> 12;
    int grp = lane >> 2, tig = lane & 3;
    int g = mt * 16 + grp + 8 * (reg & 1);
    int k = kt * 16 + 2 * tig + 8 * (reg >> 1);
    float a = Wh[(size_t)g * HID_ + k];
    float b = Wh[(size_t)g * HID_ + k + 1];
    g_WhFh[gid] = pkbf(__bfloat162float(__float2bfloat16_rn(a)),
                       __bfloat162float(__float2bfloat16_rn(b)));
}

// ---------------------------------------------------------------------------
// Kernel A: i2h (R8 winner, unchanged). Grid 512 = gc(8) x b(16) x ic(4).
// ---------------------------------------------------------------------------
#define A_HI  0
#define A_LO  24576
#define XS_HI 49152
#define XS_LO 68160
#define STGB  49152
#define SMEM_I2H 87168

__global__ void __launch_bounds__(256, 2)
i2h_kernel()
{
    extern __shared__ char sm[];
    const int gc = blockIdx.x & 7;
    const int b  = (blockIdx.x >> 3) & 15;
    const int ic = blockIdx.x >> 7;
    const int tid  = threadIdx.x;
    const int lane = tid & 31;
    const int warp = tid >> 5;
    const int wg   = warp >> 2;
    const int wn   = warp & 3;
    const int grp  = lane >> 2;
    const int tig  = lane & 3;

    uint4* ah4 = reinterpret_cast<uint4*>(sm + A_HI);
    uint4* al4 = reinterpret_cast<uint4*>(sm + A_LO);
    const uint4* wfh4 = reinterpret_cast<const uint4*>(g_WiFh);
    const uint4* wfl4 = reinterpret_cast<const uint4*>(g_WiFl);

    for (int idx = tid; idx < 1536; idx += 256) {
        int ln = idx & 31, gt = (idx >> 5) & 3, kt = (idx >> 7) & 3, kw = idx >> 9;
        int src = ((kw * 4 + kt) * 32 + gc * 4 + gt) * 32 + ln;
        int dst = ((kw * 4 + kt) * 4 + gt) * 32 + ln;
        ah4[dst] = wfh4[src];
        al4[dst] = wfl4[src];
    }

    int nbase[4];
#pragma unroll
    for (int nt2 = 0; nt2 < 4; nt2++) {
        int n = (wn * 4 + nt2) * 8 + grp;
        int hs = n >> 6, w = n & 63;
        nbase[nt2] = hs * 9504 + w * 144;
    }

    uint32_t* xh = reinterpret_cast<uint32_t*>(sm + XS_HI);
    uint32_t* xl = reinterpret_cast<uint32_t*>(sm + XS_LO);
    float* stg = reinterpret_cast<float*>(sm + STGB);

    for (int i = 0; i < 8; i++) {
        const int it = ic * 8 + i;
        const int h0 = it * 2;
        __syncthreads();

        for (int idx = tid; idx < 2 * 66 * 32; idx += 256) {
            int hs = idx >> 11;
            int rem = idx - hs * 2112;
            int wp = rem >> 5, cq = rem & 31;
            size_t g = (((size_t)b * H_ + h0 + hs) * 66 + wp) * 32 + cq;
            int d = hs * 2376 + wp * 36 + cq;
            xh[d] = g_xTh[g];
            xl[d] = g_xTl[g];
        }
        __syncthreads();

        float d[2][4][4];
#pragma unroll
        for (int a = 0; a < 2; a++)
#pragma unroll
            for (int c = 0; c < 4; c++)
#pragma unroll
                for (int r = 0; r < 4; r++) d[a][c][r] = 0.f;

#pragma unroll
        for (int kk = 0; kk < 12; kk++) {
            const int kw = kk >> 2, kt = kk & 3;
            const int koff = kw * 144 + kt * 32 + tig * 4;

            uint4 ahf[2], alf[2];
#pragma unroll
            for (int gt2 = 0; gt2 < 2; gt2++) {
                int fo = (kk * 4 + wg * 2 + gt2) * 32 + lane;
                ahf[gt2] = ah4[fo];
                alf[gt2] = al4[fo];
            }
            uint32_t bhf[4][2], blf[4][2];
#pragma unroll
            for (int nt2 = 0; nt2 < 4; nt2++) {
                int off = nbase[nt2] + koff;
                bhf[nt2][0] = *reinterpret_cast<const uint32_t*>(sm + XS_HI + off);
                bhf[nt2][1] = *reinterpret_cast<const uint32_t*>(sm + XS_HI + off + 16);
                blf[nt2][0] = *reinterpret_cast<const uint32_t*>(sm + XS_LO + off);
                blf[nt2][1] = *reinterpret_cast<const uint32_t*>(sm + XS_LO + off + 16);
            }
#pragma unroll
            for (int gt2 = 0; gt2 < 2; gt2++)
#pragma unroll
                for (int nt2 = 0; nt2 < 4; nt2++)
                    mma_bf16(d[gt2][nt2], &ahf[gt2].x, bhf[nt2]);
#pragma unroll
            for (int gt2 = 0; gt2 < 2; gt2++)
#pragma unroll
                for (int nt2 = 0; nt2 < 4; nt2++)
                    mma_bf16(d[gt2][nt2], &ahf[gt2].x, blf[nt2]);
#pragma unroll
            for (int gt2 = 0; gt2 < 2; gt2++)
#pragma unroll
                for (int nt2 = 0; nt2 < 4; nt2++)
                    mma_bf16(d[gt2][nt2], &alf[gt2].x, bhf[nt2]);
        }
        __syncthreads();

#pragma unroll
        for (int gt2 = 0; gt2 < 2; gt2++) {
            int g0 = (wg * 2 + gt2) * 16 + grp;
#pragma unroll
            for (int nt2 = 0; nt2 < 4; nt2++) {
                int n0 = (wn * 4 + nt2) * 8 + 2 * tig;
                stg[n0 * 64 + g0]           = d[gt2][nt2][0];
                stg[(n0 + 1) * 64 + g0]     = d[gt2][nt2][1];
                stg[n0 * 64 + g0 + 8]       = d[gt2][nt2][2];
                stg[(n0 + 1) * 64 + g0 + 8] = d[gt2][nt2][3];
            }
        }
        __syncthreads();

#pragma unroll
        for (int u = 0; u < 8; u++) {
            int idx = tid + u * 256;
            int n = idx >> 4;
            int q4 = idx & 15;
            float4 v = *reinterpret_cast<const float4*>(&stg[n * 64 + q4 * 4]);
            size_t dst = ((size_t)(h0 + (n >> 6)) * B_ + b) * (W_ * G_)
                       + (size_t)(n & 63) * G_ + gc * 64 + q4 * 4;
            *reinterpret_cast<float4*>(&g_i2h[dst]) = v;
        }
    }
}

// ---------------------------------------------------------------------------
// Kernel B: recurrent scan via mma, 2-pass, Wh register-resident.
// 128 blocks = (b, w8), 512 thr. Per warp: 2 mt tiles held as 16 uint4 regs.
// ---------------------------------------------------------------------------
#define GBS 516   // gbuf row stride (floats)
#define HBS 136   // h bf16 row stride (bf16 units) = 272 B
#define HP  10    // hfp row stride

__global__ void __launch_bounds__(512, 1)
rec_kernel(const float* __restrict__ bi, const float* __restrict__ bh,
           float* __restrict__ out)
{
    const int b  = blockIdx.x >> 3;
    const int w0 = (blockIdx.x & 7) * 8;
    const int t  = threadIdx.x;
    const int lane = t & 31;
    const int warp = t >> 5;        // 0..15
    const int grp  = lane >> 2;
    const int tig  = lane & 3;

    __shared__ __nv_bfloat16 hbh[8 * HBS];   // [col][k] hi
    __shared__ __nv_bfloat16 hbl[8 * HBS];   // lo
    __shared__ float hfp[HID_ * HP];         // [d][col] fp32 (out staging)
    __shared__ float gbuf[8 * GBS];          // [col][gate]

    for (int p = t; p < 8 * HBS; p += 512) {
        hbh[p] = __float2bfloat16(0.f);
        hbl[p] = __float2bfloat16(0.f);
    }
    __syncthreads();

    float bias_i[2], bias_f[2], bias_o[2], bias_g[2];
#pragma unroll
    for (int pp = 0; pp < 2; pp++) {
        int d = (t + pp * 512) & 127;
        bias_i[pp] = bi[d] + bh[d];
        bias_f[pp] = bi[HID_ + d] + bh[HID_ + d];
        bias_o[pp] = bi[2 * HID_ + d] + bh[2 * HID_ + d];
        bias_g[pp] = bi[3 * HID_ + d] + bh[3 * HID_ + d];
    }
    float creg[2] = {0.f, 0.f};

    // ---- hoist Wh fragments into registers: 2 mt x 8 kt = 16 uint4 ----
    const uint4* whfh = reinterpret_cast<const uint4*>(g_WhFh);
    const int mt0 = warp * 2;
    uint4 whr[16];
#pragma unroll
    for (int kt = 0; kt < 8; kt++) {
        whr[2 * kt]     = whfh[(kt * 32 + mt0) * 32 + lane];
        whr[2 * kt + 1] = whfh[(kt * 32 + mt0 + 1) * 32 + lane];
    }

    const int bofs = grp * (HBS * 2) + tig * 4;

    // pointwise (col,d) indices for the 2 sub-iterations
    int pcol[2], pd[2];
#pragma unroll
    for (int pp = 0; pp < 2; pp++) {
        int p = t + pp * 512;
        pcol[pp] = p >> 7;
        pd[pp]   = p & 127;
    }

    for (int row = 0; row < H_; row++) {
        // ---- issue i2h gate loads early (consumed after mma) ----
        float ivr[2][4];
#pragma unroll
        for (int pp = 0; pp < 2; pp++) {
            const float* iv = &g_i2h[((((size_t)row * B_ + b) * W_) + w0 + pcol[pp]) * G_ + pd[pp]];
            ivr[pp][0] = __ldg(iv);
            ivr[pp][1] = __ldg(iv + HID_);
            ivr[pp][2] = __ldg(iv + 2 * HID_);
            ivr[pp][3] = __ldg(iv + 3 * HID_);
        }

        // ---- mma: 2 mt x 8 kt x 2 passes; Wh from registers, h from smem ----
        float d0[4] = {0.f, 0.f, 0.f, 0.f};
        float d1[4] = {0.f, 0.f, 0.f, 0.f};
#pragma unroll
        for (int kt = 0; kt < 8; kt++) {
            uint32_t bhf[2], blf[2];
            const char* ph = reinterpret_cast<const char*>(hbh) + bofs + kt * 32;
            const char* pl = reinterpret_cast<const char*>(hbl) + bofs + kt * 32;
            bhf[0] = *reinterpret_cast<const uint32_t*>(ph);
            bhf[1] = *reinterpret_cast<const uint32_t*>(ph + 16);
            blf[0] = *reinterpret_cast<const uint32_t*>(pl);
            blf[1] = *reinterpret_cast<const uint32_t*>(pl + 16);
            mma_bf16(d0, &whr[2 * kt].x, bhf);
            mma_bf16(d1, &whr[2 * kt + 1].x, bhf);
            mma_bf16(d0, &whr[2 * kt].x, blf);
            mma_bf16(d1, &whr[2 * kt + 1].x, blf);
        }

        // ---- D -> gbuf[col][gate] ----
        {
            int g0 = mt0 * 16 + grp;
            gbuf[(2 * tig) * GBS + g0]          = d0[0];
            gbuf[(2 * tig + 1) * GBS + g0]      = d0[1];
            gbuf[(2 * tig) * GBS + g0 + 8]      = d0[2];
            gbuf[(2 * tig + 1) * GBS + g0 + 8]  = d0[3];
            int g1 = g0 + 16;
            gbuf[(2 * tig) * GBS + g1]          = d1[0];
            gbuf[(2 * tig + 1) * GBS + g1]      = d1[1];
            gbuf[(2 * tig) * GBS + g1 + 8]      = d1[2];
            gbuf[(2 * tig + 1) * GBS + g1 + 8]  = d1[3];
        }
        __syncthreads();

        // ---- pointwise: 1024 (col,d) pairs / 512 threads, c in regs ----
#pragma unroll
        for (int pp = 0; pp < 2; pp++) {
            int col = pcol[pp];
            int d   = pd[pp];
            const float* gb = &gbuf[col * GBS];
            float ig = gb[d]            + ivr[pp][0] + bias_i[pp];
            float fg = gb[HID_ + d]     + ivr[pp][1] + bias_f[pp];
            float og = gb[2 * HID_ + d] + ivr[pp][2] + bias_o[pp];
            float gg = gb[3 * HID_ + d] + ivr[pp][3] + bias_g[pp];
            float cv = sigmf(fg) * creg[pp] + sigmf(ig) * tanhf_(gg);
            float hv = sigmf(og) * tanhf_(cv);
            creg[pp] = cv;
            hfp[d * HP + col] = hv;
            float hh, hl;
            split2(hv, hh, hl);
            hbh[col * HBS + d] = __float2bfloat16(hh);
            hbl[col * HBS + d] = __float2bfloat16(hl);
        }
        __syncthreads();

        // ---- out write: out[b][d][row][w0..w0+8) ----
        if (t < HID_) {
            const int d = t;
            float4 v0 = make_float4(hfp[d * HP + 0], hfp[d * HP + 1],
                                    hfp[d * HP + 2], hfp[d * HP + 3]);
            float4 v1 = make_float4(hfp[d * HP + 4], hfp[d * HP + 5],
                                    hfp[d * HP + 6], hfp[d * HP + 7]);
            float* op = out + ((((size_t)b * HID_ + d) * H_) + row) * W_ + w0;
            *reinterpret_cast<float4*>(op)     = v0;
            *reinterpret_cast<float4*>(op + 4) = v1;
        }
        __syncthreads();
    }
}

// ---------------------------------------------------------------------------
extern "C" void kernel_launch(void* const* d_in, const int* in_sizes, int n_in,
                              void* d_out, int out_size)
{
    (void)in_sizes; (void)n_in; (void)out_size;
    const float* x  = (const float*)d_in[0];
    const float* Wi = (const float*)d_in[1];
    const float* bi = (const float*)d_in[2];
    const float* Wh = (const float*)d_in[3];
    const float* bh = (const float*)d_in[4];
    float* out = (float*)d_out;

    static bool attr_set = false;
    if (!attr_set) {
        cudaFuncSetAttribute(i2h_kernel, cudaFuncAttributeMaxDynamicSharedMemorySize, SMEM_I2H);
        attr_set = true;
    }

    prep_x<<<B_ * H_, 256>>>(x);
    prep_wif<<<96, 512>>>(Wi);
    prep_whf<<<64, 512>>>(Wh);
    i2h_kernel<<<512, 256, SMEM_I2H>>>();
    rec_kernel<<<B_ * (W_ / 8), 512>>>(bi, bh, out);
}